// round 3
// baseline (speedup 1.0000x reference)
#include <cuda_runtime.h>
#include <cuda_bf16.h>

// Problem constants
#define B_   16
#define T_   8
#define CIN  64
#define COUT 64
#define HH   56
#define WW   56
#define HWSZ (HH*WW)          // 3136
#define CH_STRIDE (T_*HWSZ)   // 25088 (stride between channels in x/out)

#define CI_CHUNK 8
#define CO_BLK   32
#define ROW_TILE 8
#define TPB      224          // 28 x 8

typedef unsigned long long ull;

__device__ __forceinline__ ull pack2(float lo, float hi) {
    ull r;
    asm("mov.b64 %0, {%1,%2};" : "=l"(r) : "f"(lo), "f"(hi));
    return r;
}

__device__ __forceinline__ void unpack2(ull v, float& lo, float& hi) {
    asm("mov.b64 {%0,%1}, %2;" : "=f"(lo), "=f"(hi) : "l"(v));
}

__device__ __forceinline__ void ffma2(ull& d, ull a, ull b) {
#if defined(__CUDA_ARCH__) && (__CUDA_ARCH__ >= 1000)
    // d = a*b + d  (packed 2x fp32, Blackwell f32x2 pipe)
    asm("fma.rn.f32x2 %0, %1, %2, %3;" : "=l"(d) : "l"(a), "l"(b), "l"(d));
#else
    float alo, ahi, blo, bhi, dlo, dhi;
    unpack2(a, alo, ahi); unpack2(b, blo, bhi); unpack2(d, dlo, dhi);
    dlo = fmaf(alo, blo, dlo);
    dhi = fmaf(ahi, bhi, dhi);
    d = pack2(dlo, dhi);
#endif
}

__global__ void __launch_bounds__(TPB, 2)
tada_conv_kernel(const float* __restrict__ x,
                 const float* __restrict__ rw,
                 const float* __restrict__ wt,
                 float* __restrict__ out)
{
    // Shared: input tile (scaled, halo, zero-padded) + pair-duplicated weights
    __shared__ __align__(16) float sIn[CI_CHUNK * 10 * 60];      // 19200 B
    __shared__ __align__(16) float sW [CI_CHUNK * 9 * CO_BLK*2]; // 18432 B

    const int tx  = threadIdx.x;           // 0..27  -> pixel pair
    const int ty  = threadIdx.y;           // 0..7   -> row within tile
    const int tid = ty * 28 + tx;

    const int coBase = blockIdx.x * CO_BLK;   // 0 or 32
    const int h0     = blockIdx.y * ROW_TILE; // 0..48
    const int bt     = blockIdx.z;            // 0..127
    const int b      = bt >> 3;
    const int t      = bt & 7;

    const int w0 = tx * 2;

    ull acc[CO_BLK];
#pragma unroll
    for (int i = 0; i < CO_BLK; ++i) acc[i] = 0ull;

    // x[b, ci, t, h, w] = ((b*CIN + ci)*T_ + t)*HWSZ + h*WW + w
    const long xBase = ((long)b * CIN * T_ + t) * HWSZ;

    for (int cc = 0; cc < CIN; cc += CI_CHUNK) {
        __syncthreads();

        // ---- load input tile: CI_CHUNK x 10 rows x 58 cols (scaled, padded) ----
        for (int idx = tid; idx < CI_CHUNK * 10 * 58; idx += TPB) {
            int c    = idx % 58;
            int rest = idx / 58;
            int r    = rest % 10;
            int ci   = rest / 10;
            int gh   = h0 - 1 + r;
            int gw   = c - 1;
            const float scale = __ldg(&rw[(b * CIN + cc + ci) * T_ + t]);
            float v  = 0.0f;
            if ((unsigned)gh < (unsigned)HH && (unsigned)gw < (unsigned)WW) {
                v = __ldg(&x[xBase + (long)(cc + ci) * CH_STRIDE + gh * WW + gw]) * scale;
            }
            sIn[(ci * 10 + r) * 60 + c] = v;
        }

        // ---- load weights, duplicated per pair: sW[(ci*9+tap)*64 + 2*co + {0,1}] ----
        for (int idx = tid; idx < CI_CHUNK * 9 * CO_BLK; idx += TPB) {
            int co   = idx % CO_BLK;
            int rest = idx / CO_BLK;
            int tap  = rest % 9;
            int ci   = rest / 9;
            float wv = __ldg(&wt[((coBase + co) * CIN + cc + ci) * 9 + tap]);
            int off  = (ci * 9 + tap) * (CO_BLK * 2) + co * 2;
            sW[off]     = wv;
            sW[off + 1] = wv;
        }
        __syncthreads();

        // ---- compute ----
#pragma unroll 1
        for (int ci = 0; ci < CI_CHUNK; ++ci) {
            // Build 9 packed input pairs for this thread's output pair
            ull p[9];
#pragma unroll
            for (int rr = 0; rr < 3; ++rr) {
                const float* srow = &sIn[(ci * 10 + ty + rr) * 60 + w0];
                float a  = srow[0];
                float bb = srow[1];
                float c2 = srow[2];
                float d  = srow[3];
                p[rr * 3 + 0] = pack2(a,  bb);
                p[rr * 3 + 1] = pack2(bb, c2);
                p[rr * 3 + 2] = pack2(c2, d);
            }
#pragma unroll
            for (int tap = 0; tap < 9; ++tap) {
                const ulonglong2* wp = (const ulonglong2*)&sW[(ci * 9 + tap) * (CO_BLK * 2)];
                const ull in = p[tap];
#pragma unroll
                for (int g = 0; g < CO_BLK / 2; ++g) {
                    ulonglong2 wv = wp[g];   // LDS.128 broadcast: 2 packed weights
                    ffma2(acc[2 * g],     wv.x, in);
                    ffma2(acc[2 * g + 1], wv.y, in);
                }
            }
        }
    }

    // ---- write out: out[b, co, t, h, w] ----
    const long oBase = (((long)b * COUT + coBase) * T_ + t) * HWSZ + (h0 + ty) * WW + w0;
#pragma unroll
    for (int co = 0; co < CO_BLK; ++co) {
        float lo, hi;
        unpack2(acc[co], lo, hi);
        float2 v = make_float2(lo, hi);
        *(float2*)&out[oBase + (long)co * CH_STRIDE] = v;
    }
}

extern "C" void kernel_launch(void* const* d_in, const int* in_sizes, int n_in,
                              void* d_out, int out_size)
{
    const float* x  = (const float*)d_in[0];
    const float* rw = (const float*)d_in[1];
    const float* wt = (const float*)d_in[2];
    float* out      = (float*)d_out;

    dim3 grid(COUT / CO_BLK, HH / ROW_TILE, B_ * T_);  // (2, 7, 128)
    dim3 block(28, 8, 1);
    tada_conv_kernel<<<grid, block>>>(x, rw, wt, out);
}

// round 4
// speedup vs baseline: 1.4715x; 1.4715x over previous
#include <cuda_runtime.h>
#include <cuda_bf16.h>

#define B_   16
#define T_   8
#define CIN  64
#define COUT 64
#define HH   56
#define WW   56
#define HWSZ (HH*WW)          // 3136
#define CH_STRIDE (T_*HWSZ)   // 25088

#define TPB 224               // 8 co-groups x 28 pixel-groups

typedef unsigned long long ull;

__device__ __forceinline__ ull pack2(float lo, float hi) {
    ull r; asm("mov.b64 %0, {%1,%2};" : "=l"(r) : "f"(lo), "f"(hi)); return r;
}
__device__ __forceinline__ void unpack2(ull v, float& lo, float& hi) {
    asm("mov.b64 {%0,%1}, %2;" : "=f"(lo), "=f"(hi) : "l"(v));
}
__device__ __forceinline__ void ffma2(ull& d, ull a, ull b) {
#if defined(__CUDA_ARCH__) && (__CUDA_ARCH__ >= 1000)
    asm("fma.rn.f32x2 %0, %1, %2, %3;" : "=l"(d) : "l"(a), "l"(b), "l"(d));
#else
    float alo, ahi, blo, bhi, dlo, dhi;
    unpack2(a, alo, ahi); unpack2(b, blo, bhi); unpack2(d, dlo, dhi);
    d = pack2(fmaf(alo, blo, dlo), fmaf(ahi, bhi, dhi));
#endif
}

__global__ void __launch_bounds__(TPB, 2)
tada_conv_kernel(const float* __restrict__ x,
                 const float* __restrict__ rw,
                 const float* __restrict__ wt,
                 float* __restrict__ out)
{
    // Input tile: 8 ci x 6 rows (4 + halo) x 60 cols (58 used) = 11.5 KB
    // Weights:    8 ci x 9 taps x 64 co                        = 18.4 KB
    __shared__ __align__(16) float sIn[8 * 6 * 60];
    __shared__ __align__(16) float sW [8 * 9 * 64];

    const int tid  = threadIdx.x;
    const int cog  = tid & 7;      // 0..7  -> co group (8 couts)
    const int pxg  = tid >> 3;     // 0..27 -> pixel group
    const int row  = pxg & 3;      // 0..3  row in tile
    const int colg = pxg >> 2;     // 0..6  col group
    const int w0   = colg * 8;
    const int co0  = cog * 8;

    const int h0 = blockIdx.x * 4;      // 14 row tiles
    const int bt = blockIdx.y;          // 128 images
    const int b  = bt >> 3;
    const int t  = bt & 7;

    // acc[co_pair][pixel]: co pair = (co0+2cp, co0+2cp+1)
    ull acc[4][8];
#pragma unroll
    for (int i = 0; i < 4; ++i)
#pragma unroll
        for (int j = 0; j < 8; ++j) acc[i][j] = 0ull;

    const long xBase = ((long)b * CIN * T_ + t) * HWSZ;

    for (int cc = 0; cc < CIN; cc += 8) {
        __syncthreads();

        // ---- input tile: 8 ci x 6 rows x 58 cols, scaled + zero halo ----
        for (int i = tid; i < 8 * 6 * 58; i += TPB) {
            int c    = i % 58;
            int rest = i / 58;
            int r    = rest % 6;
            int ci   = rest / 6;
            int gh   = h0 - 1 + r;
            int gw   = c - 1;
            const float scale = __ldg(&rw[(b * CIN + cc + ci) * T_ + t]);
            float v = 0.0f;
            if ((unsigned)gh < (unsigned)HH && (unsigned)gw < (unsigned)WW)
                v = __ldg(&x[xBase + (long)(cc + ci) * CH_STRIDE + gh * WW + gw]) * scale;
            sIn[(ci * 6 + r) * 60 + c] = v;
        }

        // ---- weights: sW[(ci*9 + tap)*64 + co] ----
        for (int i = tid; i < 8 * 9 * 64; i += TPB) {
            int co   = i & 63;
            int rest = i >> 6;
            int tap  = rest % 9;
            int ci   = rest / 9;
            sW[i] = __ldg(&wt[(co * CIN + cc + ci) * 9 + tap]);
        }
        __syncthreads();

        // ---- compute: per ci, per tap-row: 3 LDS input + 10 dup-packs,
        //      then 3 dx taps reuse them against 2 LDS.128 of packed weights ----
#pragma unroll 1
        for (int ci = 0; ci < 8; ++ci) {
#pragma unroll
            for (int rr = 0; rr < 3; ++rr) {
                const float* p = &sIn[(ci * 6 + row + rr) * 60 + w0];
                float4 va = *(const float4*)(p);
                float4 vb = *(const float4*)(p + 4);
                float2 vc = *(const float2*)(p + 8);
                ull D[10];
                D[0] = pack2(va.x, va.x); D[1] = pack2(va.y, va.y);
                D[2] = pack2(va.z, va.z); D[3] = pack2(va.w, va.w);
                D[4] = pack2(vb.x, vb.x); D[5] = pack2(vb.y, vb.y);
                D[6] = pack2(vb.z, vb.z); D[7] = pack2(vb.w, vb.w);
                D[8] = pack2(vc.x, vc.x); D[9] = pack2(vc.y, vc.y);
#pragma unroll
                for (int dx = 0; dx < 3; ++dx) {
                    const float* wp = &sW[(ci * 9 + rr * 3 + dx) * 64 + co0];
                    ulonglong2 wA = *(const ulonglong2*)(wp);      // co pairs 0,1
                    ulonglong2 wB = *(const ulonglong2*)(wp + 4);  // co pairs 2,3
#pragma unroll
                    for (int px = 0; px < 8; ++px) {
                        ffma2(acc[0][px], wA.x, D[dx + px]);
                        ffma2(acc[1][px], wA.y, D[dx + px]);
                        ffma2(acc[2][px], wB.x, D[dx + px]);
                        ffma2(acc[3][px], wB.y, D[dx + px]);
                    }
                }
            }
        }
    }

    // ---- store: 8 co x 8 px per thread, float4 vectorized ----
    const long oBase = (((long)b * COUT + co0) * T_ + t) * HWSZ + (h0 + row) * WW + w0;
#pragma unroll
    for (int cp = 0; cp < 4; ++cp) {
        float e[8], o[8];
#pragma unroll
        for (int px = 0; px < 8; ++px) unpack2(acc[cp][px], e[px], o[px]);
        float4* de = (float4*)&out[oBase + (long)(2 * cp)     * CH_STRIDE];
        float4* dn = (float4*)&out[oBase + (long)(2 * cp + 1) * CH_STRIDE];
        de[0] = make_float4(e[0], e[1], e[2], e[3]);
        de[1] = make_float4(e[4], e[5], e[6], e[7]);
        dn[0] = make_float4(o[0], o[1], o[2], o[3]);
        dn[1] = make_float4(o[4], o[5], o[6], o[7]);
    }
}

extern "C" void kernel_launch(void* const* d_in, const int* in_sizes, int n_in,
                              void* d_out, int out_size)
{
    const float* x  = (const float*)d_in[0];
    const float* rw = (const float*)d_in[1];
    const float* wt = (const float*)d_in[2];
    float* out      = (float*)d_out;

    dim3 grid(HH / 4, B_ * T_);   // (14, 128)
    tada_conv_kernel<<<grid, TPB>>>(x, rw, wt, out);
}

// round 6
// speedup vs baseline: 3.6053x; 2.4500x over previous
#include <cuda_runtime.h>

#define B_   16
#define T_   8
#define CIN  64
#define COUT 64
#define HH   56
#define WW   56
#define HWSZ (HH*WW)          // 3136
#define CH_STRIDE (T_*HWSZ)   // 25088

#define TPB 256               // 8 warps: 2 m-halves x 4 output rows

__device__ __forceinline__ unsigned f2tf32(float f) {
    unsigned r; asm("cvt.rna.tf32.f32 %0, %1;" : "=r"(r) : "f"(f)); return r;
}

__device__ __forceinline__ void mma_tf32(float* d, const unsigned* a, const unsigned* b) {
    asm("mma.sync.aligned.m16n8k8.row.col.f32.tf32.tf32.f32 "
        "{%0,%1,%2,%3}, {%4,%5,%6,%7}, {%8,%9}, {%0,%1,%2,%3};"
        : "+f"(d[0]), "+f"(d[1]), "+f"(d[2]), "+f"(d[3])
        : "r"(a[0]), "r"(a[1]), "r"(a[2]), "r"(a[3]), "r"(b[0]), "r"(b[1]));
}

__global__ void __launch_bounds__(TPB)
tada_conv_mma(const float* __restrict__ x,
              const float* __restrict__ rw,
              const float* __restrict__ wt,
              float* __restrict__ out)
{
    // Input tile: 8 ci x 6 rows (4 out + halo) x 60 cols (58 used), tf32 bits. 11.5 KB
    // Weights:    9 taps x 64 co x 8 ci (padded to 12 for conflict-free frags). 27.6 KB
    __shared__ unsigned sIn[8 * 6 * 60];
    __shared__ unsigned sA [9 * 64 * 12];

    const int tid = threadIdx.x;
    const int wid = tid >> 5;
    const int lid = tid & 31;
    const int g   = lid >> 2;     // 0..7  (MMA group id)
    const int tig = lid & 3;      // 0..3  (thread-in-group)

    const int m0   = (wid & 1) * 32;   // warp covers co [m0, m0+32)
    const int orow = wid >> 1;         // warp covers output row orow of the 4-row tile

    const int h0 = blockIdx.x * 4;     // 14 row-tiles
    const int bt = blockIdx.y;         // 128 images
    const int b  = bt >> 3;
    const int t  = bt & 7;

    // acc[m-tile 0/1][n-tile 0..6][frag 0..3] : co m0+mt*16+{g,g+8}, cols nt*8+2*tig{,+1}
    float acc[2][7][4];
#pragma unroll
    for (int i = 0; i < 2; ++i)
#pragma unroll
        for (int j = 0; j < 7; ++j)
#pragma unroll
            for (int k = 0; k < 4; ++k) acc[i][j][k] = 0.0f;

    const long xBase = ((long)b * CIN * T_ + t) * HWSZ;

    for (int cc = 0; cc < CIN; cc += 8) {
        __syncthreads();

        // ---- fill input tile (routing scale fused, tf32-converted, zero halo) ----
        for (int i = tid; i < 8 * 6 * 58; i += TPB) {
            int c    = i % 58;
            int rest = i / 58;
            int r    = rest % 6;
            int ci   = rest / 6;
            int gh   = h0 - 1 + r;
            int gw   = c - 1;
            const float scale = __ldg(&rw[(b * CIN + cc + ci) * T_ + t]);
            float v = 0.0f;
            if ((unsigned)gh < (unsigned)HH && (unsigned)gw < (unsigned)WW)
                v = __ldg(&x[xBase + (long)(cc + ci) * CH_STRIDE + gh * WW + gw]) * scale;
            sIn[(ci * 6 + r) * 60 + c] = f2tf32(v);
        }

        // ---- fill weights: sA[(tap*64 + co)*12 + ci]  (STS conflict-free order) ----
        for (int i = tid; i < 9 * 64 * 8; i += TPB) {
            int ci   = i & 7;
            int rest = i >> 3;
            int co   = rest & 63;
            int tap  = rest >> 6;
            float v  = __ldg(&wt[(co * CIN + cc + ci) * 9 + tap]);
            sA[(tap * 64 + co) * 12 + ci] = f2tf32(v);
        }
        __syncthreads();

        // ---- 9 taps = 9 k-accumulation steps of m32 x n56 x k8 per warp ----
#pragma unroll
        for (int tap = 0; tap < 9; ++tap) {
            const int rr = tap / 3;   // tap row 0..2
            const int dx = tap % 3;   // tap col 0..2

            // A fragments for both m-tiles (conflict-free: pad-12 layout)
            unsigned a[2][4];
            const unsigned* wbase = &sA[tap * 64 * 12];
#pragma unroll
            for (int mt = 0; mt < 2; ++mt) {
                const int co = m0 + mt * 16 + g;
                a[mt][0] = wbase[co * 12 + tig];
                a[mt][1] = wbase[(co + 8) * 12 + tig];
                a[mt][2] = wbase[co * 12 + tig + 4];
                a[mt][3] = wbase[(co + 8) * 12 + tig + 4];
            }

            // B fragments: B[k=ci][n=col] = sIn[ci][orow+rr][n0 + g + dx]
            const unsigned* brow0 = &sIn[((tig)     * 6 + orow + rr) * 60 + dx + g];
            const unsigned* brow1 = &sIn[((tig + 4) * 6 + orow + rr) * 60 + dx + g];
#pragma unroll
            for (int nt = 0; nt < 7; ++nt) {
                unsigned bf[2];
                bf[0] = brow0[nt * 8];
                bf[1] = brow1[nt * 8];
                mma_tf32(acc[0][nt], a[0], bf);
                mma_tf32(acc[1][nt], a[1], bf);
            }
        }
    }

    // ---- store: c0,c1 -> (co, col..col+1); c2,c3 -> (co+8, ...) ----
#pragma unroll
    for (int mt = 0; mt < 2; ++mt) {
        const int co = m0 + mt * 16 + g;
        const long oRow = (((long)b * COUT + co) * T_ + t) * HWSZ + (h0 + orow) * WW;
#pragma unroll
        for (int nt = 0; nt < 7; ++nt) {
            const int col = nt * 8 + tig * 2;
            *(float2*)&out[oRow + col] =
                make_float2(acc[mt][nt][0], acc[mt][nt][1]);
            *(float2*)&out[oRow + 8L * CH_STRIDE + col] =
                make_float2(acc[mt][nt][2], acc[mt][nt][3]);
        }
    }
}

extern "C" void kernel_launch(void* const* d_in, const int* in_sizes, int n_in,
                              void* d_out, int out_size)
{
    const float* x  = (const float*)d_in[0];
    const float* rw = (const float*)d_in[1];
    const float* wt = (const float*)d_in[2];
    float* out      = (float*)d_out;

    dim3 grid(HH / 4, B_ * T_);   // (14, 128)
    tada_conv_mma<<<grid, TPB>>>(x, rw, wt, out);
}